// round 13
// baseline (speedup 1.0000x reference)
#include <cuda_runtime.h>
#include <cuda_fp16.h>
#include <cuda_bf16.h>
#include <stdint.h>
#include <math.h>

#define NTYPES 10000
#define NG     2000
#define NB     1024

// ---------------- scratch (device globals) ----------------
__device__ unsigned char g_IW8[NTYPES * 128];  // impact @ W.T  (e5m2)
__device__ unsigned char g_IM8[NTYPES * 128];  // impact @ M.T  (e5m2)
__device__ __half g_W1h[128 * 256];            // W1 in fp16
__device__ float  g_E [NG * 128];              // softmax(per_graph)
__device__ float  g_X [NG * 128];              // softmax(relu(ext))

typedef unsigned long long u64t;
__device__ __forceinline__ float2 upk2(u64t v) {
    unsigned lo, hi;
    asm("mov.b64 {%0, %1}, %2;" : "=r"(lo), "=r"(hi) : "l"(v));
    return make_float2(__uint_as_float(lo), __uint_as_float(hi));
}
#define FMA2(d, a, b) asm("fma.rn.f32x2 %0, %1, %2, %0;" : "+l"(d) : "l"(a), "l"(b))

__device__ __forceinline__ unsigned short f2_to_e5m2x2(float lo, float hi) {
    unsigned short r;
    asm("cvt.rn.satfinite.e5m2x2.f32 %0, %1, %2;" : "=h"(r) : "f"(hi), "f"(lo));
    return r;  // low byte <- lo
}
__device__ __forceinline__ unsigned prmt(unsigned a, unsigned b, unsigned s) {
    unsigned d;
    asm("prmt.b32 %0, %1, %2, %3;" : "=r"(d) : "r"(a), "r"(b), "r"(s));
    return d;
}
#define E5M2_LO(u) (prmt((u), 0u, 0x1404u))
#define E5M2_HI(u) (prmt((u), 0u, 0x3424u))
__device__ __forceinline__ __half2 asx(unsigned u) { return *(__half2*)&u; }

__device__ __forceinline__ void cpa16(unsigned daddr, const void* src) {
    asm volatile("cp.async.cg.shared.global [%0], [%1], 16;" :: "r"(daddr), "l"(src));
}
__device__ __forceinline__ unsigned smem_u32(const void* p) {
    unsigned a;
    asm("{ .reg .u64 t; cvta.to.shared.u64 t, %1; cvt.u32.u64 %0, t; }" : "=r"(a) : "l"(p));
    return a;
}

// ---------------- mma.sync (sm_80+, legal on base sm_103 target) ------------
__device__ __forceinline__ void ldsm_x4(unsigned& r0, unsigned& r1,
                                        unsigned& r2, unsigned& r3, unsigned addr) {
    asm volatile("ldmatrix.sync.aligned.m8n8.x4.shared.b16 {%0,%1,%2,%3}, [%4];"
                 : "=r"(r0), "=r"(r1), "=r"(r2), "=r"(r3) : "r"(addr));
}
__device__ __forceinline__ void ldsm_x2t(unsigned& r0, unsigned& r1, unsigned addr) {
    asm volatile("ldmatrix.sync.aligned.m8n8.x2.trans.shared.b16 {%0,%1}, [%2];"
                 : "=r"(r0), "=r"(r1) : "r"(addr));
}
__device__ __forceinline__ void mma16816(float* d, const unsigned* a,
                                         unsigned b0, unsigned b1) {
    asm volatile(
        "mma.sync.aligned.m16n8k16.row.col.f32.bf16.bf16.f32 "
        "{%0,%1,%2,%3}, {%4,%5,%6,%7}, {%8,%9}, {%0,%1,%2,%3};"
        : "+f"(d[0]), "+f"(d[1]), "+f"(d[2]), "+f"(d[3])
        : "r"(a[0]), "r"(a[1]), "r"(a[2]), "r"(a[3]), "r"(b0), "r"(b1));
}

// ============================================================================
// Kernel A (HMMA): IW/IM = impact @ {W,M}.T -> e5m2 tables.   (unchanged R12)
// ============================================================================
#define KA_STR 136
#define SMEM_A (3 * 128 * KA_STR * 2 + 16)

__global__ void __launch_bounds__(256) kA(const float* __restrict__ impact,
                                          const float* __restrict__ W,
                                          const float* __restrict__ M,
                                          const float* __restrict__ W1) {
    extern __shared__ __half smh[];
    __half* sA = smh;                    // [128][KA_STR]
    __half* sW = smh + 128 * KA_STR;
    __half* sM = sW + 128 * KA_STR;

    const int tid = threadIdx.x;
    const int warp = tid >> 5, lane = tid & 31;
    const int rowBase = blockIdx.x * 128;

    if (blockIdx.x < 16) {
        const int base = blockIdx.x * 2048;
        for (int q = tid; q < 1024; q += 256) {
            const float2 v = *(const float2*)(W1 + base + (q << 1));
            *(__half2*)(g_W1h + base + (q << 1)) = __floats2half2_rn(v.x, v.y);
        }
    }

    for (int idx = tid; idx < 128 * 64; idx += 256) {
        const int r = idx >> 6, cp = (idx & 63) << 1;
        const int grow = rowBase + r;
        const float2 av = (grow < NTYPES) ? *(const float2*)(impact + (size_t)grow * 128 + cp)
                                          : make_float2(0.f, 0.f);
        const float2 wv = *(const float2*)(W + r * 128 + cp);
        const float2 mv = *(const float2*)(M + r * 128 + cp);
        *(__nv_bfloat162*)(sA + r * KA_STR + cp) = __floats2bfloat162_rn(av.x, av.y);
        *(__nv_bfloat162*)(sW + r * KA_STR + cp) = __floats2bfloat162_rn(wv.x, wv.y);
        *(__nv_bfloat162*)(sM + r * KA_STR + cp) = __floats2bfloat162_rn(mv.x, mv.y);
    }
    __syncthreads();

    const unsigned sbase = smem_u32(smh);
    const int wrb = warp << 4;

    const int aRow = wrb + (lane & 15);
    const unsigned aBase = sbase + ((unsigned)(aRow * KA_STR + ((lane >> 4) << 3)) << 1);
    unsigned a[8][4];
#pragma unroll
    for (int k = 0; k < 8; ++k)
        ldsm_x4(a[k][0], a[k][1], a[k][2], a[k][3], aBase + (k << 5));

    const unsigned bOff = ((unsigned)((lane & 7) * KA_STR + (((lane >> 3) & 1) << 3)) << 1);
    const unsigned wB = sbase + 128 * KA_STR * 2 + bOff;
    const unsigned mB = sbase + 2 * 128 * KA_STR * 2 + bOff;

    const int r0g = rowBase + wrb + (lane >> 2);
    const int r1g = r0g + 8;
    const int cbase = (lane & 3) << 1;

#pragma unroll
    for (int t = 0; t < 2; ++t) {
        const unsigned bb = t ? mB : wB;
        unsigned char* dst = t ? g_IM8 : g_IW8;
        float acc[16][4];
#pragma unroll
        for (int n = 0; n < 16; ++n) {
            acc[n][0] = acc[n][1] = acc[n][2] = acc[n][3] = 0.f;
        }
#pragma unroll
        for (int n = 0; n < 16; ++n) {
            const unsigned bn = bb + (unsigned)(n * 8 * KA_STR * 2);
#pragma unroll
            for (int k = 0; k < 8; ++k) {
                unsigned b0, b1;
                ldsm_x2t(b0, b1, bn + (k << 5));
                mma16816(acc[n], a[k], b0, b1);
            }
        }
#pragma unroll
        for (int n = 0; n < 16; ++n) {
            const unsigned short u0 = f2_to_e5m2x2(acc[n][0], acc[n][1]);
            const unsigned short u1 = f2_to_e5m2x2(acc[n][2], acc[n][3]);
            const int col = (n << 3) + cbase;
            if (r0g < NTYPES) *(unsigned short*)(dst + (size_t)r0g * 128 + col) = u0;
            if (r1g < NTYPES) *(unsigned short*)(dst + (size_t)r1g * 128 + col) = u1;
        }
    }
}

// ============================================================================
// Kernel B: per_graph gather-sum + softmax -> E.
// Batched loads (unroll 4 -> ~36 in flight) + tree-sum (depth 4).
// ============================================================================
__global__ void __launch_bounds__(256) kB(const int* __restrict__ node_type,
                                          const int* __restrict__ nbr_type) {
    __shared__ int   sNT[64];
    __shared__ int   sNB[512];
    __shared__ float sP[8][132];
    __shared__ float sredm[8];
    __shared__ float sreds[8];

    const int tid = threadIdx.x;
    const int g = blockIdx.x;
    const int w = tid >> 5, lane = tid & 31;

    if (tid < 64) sNT[tid] = node_type[g * 64 + tid];
    for (int idx = tid; idx < 512; idx += 256) sNB[idx] = nbr_type[g * 512 + idx];
    __syncthreads();

    const int co = lane << 2;
    float4 acc = make_float4(0.f, 0.f, 0.f, 0.f);
#pragma unroll 4
    for (int kk = 0; kk < 8; ++kk) {
        const int k = (kk << 3) + w;
        const unsigned u = *(const unsigned*)(g_IW8 + (size_t)sNT[k] * 128 + co);
        const int* nbp = &sNB[k << 3];
        unsigned vv[8];
#pragma unroll
        for (int d = 0; d < 8; ++d)
            vv[d] = *(const unsigned*)(g_IM8 + (size_t)nbp[d] * 128 + co);

        // tree-sum lo halves
        __half2 l0 = __hadd2(asx(E5M2_LO(vv[0])), asx(E5M2_LO(vv[1])));
        __half2 l1 = __hadd2(asx(E5M2_LO(vv[2])), asx(E5M2_LO(vv[3])));
        __half2 l2 = __hadd2(asx(E5M2_LO(vv[4])), asx(E5M2_LO(vv[5])));
        __half2 l3 = __hadd2(asx(E5M2_LO(vv[6])), asx(E5M2_LO(vv[7])));
        l0 = __hadd2(l0, l1);
        l2 = __hadd2(l2, l3);
        const __half2 s01 = __hadd2(asx(E5M2_LO(u)), __hadd2(l0, l2));
        // tree-sum hi halves
        __half2 h0 = __hadd2(asx(E5M2_HI(vv[0])), asx(E5M2_HI(vv[1])));
        __half2 h1 = __hadd2(asx(E5M2_HI(vv[2])), asx(E5M2_HI(vv[3])));
        __half2 h2 = __hadd2(asx(E5M2_HI(vv[4])), asx(E5M2_HI(vv[5])));
        __half2 h3 = __hadd2(asx(E5M2_HI(vv[6])), asx(E5M2_HI(vv[7])));
        h0 = __hadd2(h0, h1);
        h2 = __hadd2(h2, h3);
        const __half2 s23 = __hadd2(asx(E5M2_HI(u)), __hadd2(h0, h2));

        const float2 f01 = __half22float2(s01);
        const float2 f23 = __half22float2(s23);
        acc.x += fmaxf(f01.x, 0.f);
        acc.y += fmaxf(f01.y, 0.f);
        acc.z += fmaxf(f23.x, 0.f);
        acc.w += fmaxf(f23.y, 0.f);
    }
    *(float4*)(&sP[w][co]) = acc;
    __syncthreads();

    float v = 0.f;
    if (tid < 128) {
#pragma unroll
        for (int ww = 0; ww < 8; ++ww) v += sP[ww][tid];
    }
    float m = v;
#pragma unroll
    for (int off = 16; off; off >>= 1)
        m = fmaxf(m, __shfl_xor_sync(0xffffffffu, m, off));
    if (lane == 0) sredm[w] = m;
    __syncthreads();
    const float M = fmaxf(fmaxf(sredm[0], sredm[1]), fmaxf(sredm[2], sredm[3]));

    const float e = (tid < 128) ? expf(v - M) : 0.f;
    float s = e;
#pragma unroll
    for (int off = 16; off; off >>= 1)
        s += __shfl_xor_sync(0xffffffffu, s, off);
    if (lane == 0) sreds[w] = s;
    __syncthreads();
    const float tot = sreds[0] + sreds[1] + sreds[2] + sreds[3];

    if (tid < 128) g_E[g * 128 + tid] = e / tot;
}

// ============================================================================
// Kernel C: ext = E @ U.T + Esum @ V.T ;  X = softmax(relu(ext))
// Zero-pack: sEt/sSt duplicated rows; U/V column-pairs native u64.
// ============================================================================
#define C_WSTR 132
#define C_ASTR2 72
#define SMEM_C ((2 * 128 * C_WSTR + 2 * 128 * C_ASTR2) * 4 + 512 * 4)

__global__ void __launch_bounds__(256) kC(const float* __restrict__ U,
                                          const float* __restrict__ V,
                                          const int* __restrict__ ext_nbr) {
    extern __shared__ float sm[];
    float* sUt = sm;
    float* sVt = sUt + 128 * C_WSTR;
    float* sEt = sVt + 128 * C_WSTR;     // [128][C_ASTR2] duplicated E^T
    float* sSt = sEt + 128 * C_ASTR2;    // [128][C_ASTR2] duplicated Esum^T
    int*   sXN = (int*)(sSt + 128 * C_ASTR2);

    const int tid = threadIdx.x;
    const int rowBase = blockIdx.x * 32;

    for (int idx = tid; idx < 128 * 128; idx += 256) {
        int j = idx >> 7, i = idx & 127;
        sUt[i * C_WSTR + j] = U[idx];
        sVt[i * C_WSTR + j] = V[idx];
    }
    for (int idx = tid; idx < 32 * 128; idx += 256) {
        int r = idx >> 7, i = idx & 127;
        int row = rowBase + r;
        const float v = (row < NG) ? g_E[row * 128 + i] : 0.f;
        sEt[i * C_ASTR2 + (r << 1)] = v;
        sEt[i * C_ASTR2 + (r << 1) + 1] = v;
    }
    for (int idx = tid; idx < 512; idx += 256) {
        int row = rowBase + (idx >> 4);
        sXN[idx] = (row < NG) ? ext_nbr[row * 16 + (idx & 15)] : 0;
    }
    __syncthreads();

    for (int idx = tid; idx < 32 * 32; idx += 256) {
        int r = idx >> 5, c4 = (idx & 31) << 2;
        const int* xn = &sXN[r * 16];
        float4 s = make_float4(0.f, 0.f, 0.f, 0.f);
#pragma unroll
        for (int d = 0; d < 16; ++d) {
            const float4 v = *(const float4*)(g_E + xn[d] * 128 + c4);
            s.x += v.x; s.y += v.y; s.z += v.z; s.w += v.w;
        }
#pragma unroll
        for (int c = 0; c < 4; ++c) {
            const float sv = (&s.x)[c];
            sSt[(c4 + c) * C_ASTR2 + (r << 1)] = sv;
            sSt[(c4 + c) * C_ASTR2 + (r << 1) + 1] = sv;
        }
    }
    __syncthreads();

    const int tx = tid & 31;  // 4 cols: tx*4..+3 (2 u64 pairs)
    const int ty = tid >> 5;  // 4 rows: ty*4..+3
    u64t acc2[4][2] = {};     // [row][col-pair]; lanes = 2 cols of same row

#pragma unroll 4
    for (int i = 0; i < 128; ++i) {
        const u64t* up = (const u64t*)(sUt + i * C_WSTR + (tx << 2));
        const u64t* vp = (const u64t*)(sVt + i * C_WSTR + (tx << 2));
        const u64t* ep = (const u64t*)(sEt + i * C_ASTR2 + (ty << 3));
        const u64t* sp = (const u64t*)(sSt + i * C_ASTR2 + (ty << 3));
        const u64t u0 = up[0], u1 = up[1];
        const u64t v0 = vp[0], v1 = vp[1];
#pragma unroll
        for (int rr = 0; rr < 4; ++rr) {
            FMA2(acc2[rr][0], ep[rr], u0); FMA2(acc2[rr][1], ep[rr], u1);
            FMA2(acc2[rr][0], sp[rr], v0); FMA2(acc2[rr][1], sp[rr], v1);
        }
    }

#pragma unroll
    for (int rr = 0; rr < 4; ++rr) {
        const int row = rowBase + (ty << 2) + rr;
        const float2 c01 = upk2(acc2[rr][0]);
        const float2 c23 = upk2(acc2[rr][1]);
        float v0 = fmaxf(c01.x, 0.f), v1 = fmaxf(c01.y, 0.f);
        float v2 = fmaxf(c23.x, 0.f), v3 = fmaxf(c23.y, 0.f);
        float m = fmaxf(fmaxf(v0, v1), fmaxf(v2, v3));
#pragma unroll
        for (int off = 16; off; off >>= 1)
            m = fmaxf(m, __shfl_xor_sync(0xffffffffu, m, off));
        float e0 = expf(v0 - m), e1 = expf(v1 - m), e2 = expf(v2 - m), e3 = expf(v3 - m);
        float s = e0 + e1 + e2 + e3;
#pragma unroll
        for (int off = 16; off; off >>= 1)
            s += __shfl_xor_sync(0xffffffffu, s, off);
        if (row < NG) {
            const float inv = 1.f / s;
            float4 o = make_float4(e0 * inv, e1 * inv, e2 * inv, e3 * inv);
            *(float4*)(g_X + row * 128 + (tx << 2)) = o;
        }
    }
}

// ============================================================================
// Kernel D: ONE WAVE. 128 blocks x 8 rows; 512 threads; cp.async fill. (unchanged)
// ============================================================================
#define D2_STR 264
#define SMEM_D (128 * D2_STR * 2)

__global__ void __launch_bounds__(512) kD(const int* __restrict__ batch,
                                          const float* __restrict__ b1,
                                          const float* __restrict__ W2,
                                          const float* __restrict__ b2,
                                          float* __restrict__ out) {
    extern __shared__ __half sWh[];      // [128][D2_STR]
    __shared__ float sF[8][260];
    __shared__ float sW2[256];
    __shared__ float sB1[128];
    __shared__ float sP[16][2][2];

    const int tid = threadIdx.x;
    const int rg = tid >> 7;
    const int j = tid & 127;
    const int warp = tid >> 5, lane = tid & 31;

    const unsigned sbase = (unsigned)__cvta_generic_to_shared(sWh);
    for (int q = tid; q < 128 * 32; q += 512) {
        const int jr = q >> 5, i8 = (q & 31) << 3;
        cpa16(sbase + (jr * D2_STR + i8) * 2, g_W1h + (q << 3));
    }
    asm volatile("cp.async.commit_group;" ::: "memory");

    if (tid < 256) sW2[tid] = W2[tid];
    if (tid < 128) sB1[tid] = b1[tid];
    const float bb0 = b2[0], bb1 = b2[1];

    const int rb = rg << 1;
#pragma unroll
    for (int rr = 0; rr < 2; ++rr) {
        const int row = blockIdx.x * 8 + rb + rr;
        const int b0i = batch[2 * row];
        const int b1i = batch[2 * row + 1];
        const float e1 = g_X[b0i * 128 + j];
        const float e2 = g_X[b1i * 128 + j];
        sF[rb + rr][j] = e1 * e2;
        sF[rb + rr][128 + j] = e1 + e2;
    }
    asm volatile("cp.async.wait_group 0;" ::: "memory");
    __syncthreads();

    float4 a0 = make_float4(0.f, 0.f, 0.f, 0.f);
    float4 a1 = a0;
    const __half* wrow = sWh + j * D2_STR;
#pragma unroll 4
    for (int m = 0; m < 32; ++m) {
        const uint4 wv = *(const uint4*)(wrow + (m << 3));
        const float2 w01 = __half22float2(*(const __half2*)&wv.x);
        const float2 w23 = __half22float2(*(const __half2*)&wv.y);
        const float2 w45 = __half22float2(*(const __half2*)&wv.z);
        const float2 w67 = __half22float2(*(const __half2*)&wv.w);
        const float4 f0a = *(const float4*)(&sF[rb + 0][m << 3]);
        const float4 f0b = *(const float4*)(&sF[rb + 0][(m << 3) + 4]);
        const float4 f1a = *(const float4*)(&sF[rb + 1][m << 3]);
        const float4 f1b = *(const float4*)(&sF[rb + 1][(m << 3) + 4]);
        a0.x = fmaf(f0a.x, w01.x, a0.x); a0.y = fmaf(f0a.y, w01.y, a0.y);
        a0.z = fmaf(f0a.z, w23.x, a0.z); a0.w = fmaf(f0a.w, w23.y, a0.w);
        a0.x = fmaf(f0b.x, w45.x, a0.x); a0.y = fmaf(f0b.y, w45.y, a0.y);
        a0.z = fmaf(f0b.z, w67.x, a0.z); a0.w = fmaf(f0b.w, w67.y, a0.w);
        a1.x = fmaf(f1a.x, w01.x, a1.x); a1.y = fmaf(f1a.y, w01.y, a1.y);
        a1.z = fmaf(f1a.z, w23.x, a1.z); a1.w = fmaf(f1a.w, w23.y, a1.w);
        a1.x = fmaf(f1b.x, w45.x, a1.x); a1.y = fmaf(f1b.y, w45.y, a1.y);
        a1.z = fmaf(f1b.z, w67.x, a1.z); a1.w = fmaf(f1b.w, w67.y, a1.w);
    }

    const float bj = sB1[j];
    const float w2a = sW2[j], w2b = sW2[128 + j];
    const float h0 = fmaxf((a0.x + a0.y) + (a0.z + a0.w) + bj, 0.f);
    const float h1 = fmaxf((a1.x + a1.y) + (a1.z + a1.w) + bj, 0.f);

    float p00 = h0 * w2a, p01 = h0 * w2b;
    float p10 = h1 * w2a, p11 = h1 * w2b;
#pragma unroll
    for (int off = 16; off; off >>= 1) {
        p00 += __shfl_xor_sync(0xffffffffu, p00, off);
        p01 += __shfl_xor_sync(0xffffffffu, p01, off);
        p10 += __shfl_xor_sync(0xffffffffu, p10, off);
        p11 += __shfl_xor_sync(0xffffffffu, p11, off);
    }
    if (lane == 0) {
        sP[warp][0][0] = p00; sP[warp][0][1] = p01;
        sP[warp][1][0] = p10; sP[warp][1][1] = p11;
    }
    __syncthreads();

    if (tid < 8) {
        const int r = tid;
        const int wbase = (r >> 1) << 2;
        const int lr = r & 1;
        const int row = blockIdx.x * 8 + r;
        float o0 = bb0, o1 = bb1;
#pragma unroll
        for (int w2 = 0; w2 < 4; ++w2) {
            o0 += sP[wbase + w2][lr][0];
            o1 += sP[wbase + w2][lr][1];
        }
        const float mm = fmaxf(o0, o1);
        const float z0 = expf(o0 - mm), z1 = expf(o1 - mm);
        const float inv = 1.f / (z0 + z1);
        out[row * 2]     = z0 * inv;
        out[row * 2 + 1] = z1 * inv;
    }
}

// ============================================================================
extern "C" void kernel_launch(void* const* d_in, const int* in_sizes, int n_in,
                              void* d_out, int out_size) {
    const int*   batch     = (const int*)d_in[0];
    const int*   node_type = (const int*)d_in[1];
    const int*   nbr_type  = (const int*)d_in[2];
    const int*   ext_nbr   = (const int*)d_in[3];
    const float* impact    = (const float*)d_in[4];
    const float* W         = (const float*)d_in[5];
    const float* M         = (const float*)d_in[6];
    const float* U         = (const float*)d_in[7];
    const float* V         = (const float*)d_in[8];
    const float* W1        = (const float*)d_in[9];
    const float* b1        = (const float*)d_in[10];
    const float* W2        = (const float*)d_in[11];
    const float* b2        = (const float*)d_in[12];
    float* out = (float*)d_out;

    cudaFuncSetAttribute(kA, cudaFuncAttributeMaxDynamicSharedMemorySize, SMEM_A);
    cudaFuncSetAttribute(kC, cudaFuncAttributeMaxDynamicSharedMemorySize, SMEM_C);
    cudaFuncSetAttribute(kD, cudaFuncAttributeMaxDynamicSharedMemorySize, SMEM_D);

    kA<<<(NTYPES + 127) / 128, 256, SMEM_A>>>(impact, W, M, W1);
    kB<<<NG, 256>>>(node_type, nbr_type);
    kC<<<(NG + 31) / 32, 256, SMEM_C>>>(U, V, ext_nbr);
    kD<<<NB / 8, 512, SMEM_D>>>(batch, b1, W2, b2, out);
}

// round 14
// speedup vs baseline: 1.0273x; 1.0273x over previous
#include <cuda_runtime.h>
#include <cuda_fp16.h>
#include <cuda_bf16.h>
#include <stdint.h>
#include <math.h>

#define NTYPES 10000
#define NG     2000
#define NB     1024

// ---------------- scratch (device globals) ----------------
__device__ unsigned char g_IW8[NTYPES * 128];  // impact @ W.T  (e5m2)
__device__ unsigned char g_IM8[NTYPES * 128];  // impact @ M.T  (e5m2)
__device__ __half g_W1h[128 * 256];            // W1 in fp16
__device__ float  g_E [NG * 128];              // softmax(per_graph)
__device__ float  g_X [NG * 128];              // softmax(relu(ext))

typedef unsigned long long u64t;
__device__ __forceinline__ u64t pk2(float lo, float hi) {
    u64t r;
    asm("mov.b64 %0, {%1, %2};" : "=l"(r) : "r"(__float_as_uint(lo)), "r"(__float_as_uint(hi)));
    return r;
}
__device__ __forceinline__ float2 upk2(u64t v) {
    unsigned lo, hi;
    asm("mov.b64 {%0, %1}, %2;" : "=r"(lo), "=r"(hi) : "l"(v));
    return make_float2(__uint_as_float(lo), __uint_as_float(hi));
}
#define FMA2(d, a, b) asm("fma.rn.f32x2 %0, %1, %2, %0;" : "+l"(d) : "l"(a), "l"(b))

__device__ __forceinline__ unsigned short f2_to_e5m2x2(float lo, float hi) {
    unsigned short r;
    asm("cvt.rn.satfinite.e5m2x2.f32 %0, %1, %2;" : "=h"(r) : "f"(hi), "f"(lo));
    return r;  // low byte <- lo
}
__device__ __forceinline__ unsigned prmt(unsigned a, unsigned b, unsigned s) {
    unsigned d;
    asm("prmt.b32 %0, %1, %2, %3;" : "=r"(d) : "r"(a), "r"(b), "r"(s));
    return d;
}
#define E5M2_LO(u) (prmt((u), 0u, 0x1404u))
#define E5M2_HI(u) (prmt((u), 0u, 0x3424u))

__device__ __forceinline__ void cpa16(unsigned daddr, const void* src) {
    asm volatile("cp.async.cg.shared.global [%0], [%1], 16;" :: "r"(daddr), "l"(src));
}
__device__ __forceinline__ unsigned smem_u32(const void* p) {
    unsigned a;
    asm("{ .reg .u64 t; cvta.to.shared.u64 t, %1; cvt.u32.u64 %0, t; }" : "=r"(a) : "l"(p));
    return a;
}

// ---------------- mma.sync (sm_80+, legal on base sm_103 target) ------------
__device__ __forceinline__ void ldsm_x4(unsigned& r0, unsigned& r1,
                                        unsigned& r2, unsigned& r3, unsigned addr) {
    asm volatile("ldmatrix.sync.aligned.m8n8.x4.shared.b16 {%0,%1,%2,%3}, [%4];"
                 : "=r"(r0), "=r"(r1), "=r"(r2), "=r"(r3) : "r"(addr));
}
__device__ __forceinline__ void ldsm_x2t(unsigned& r0, unsigned& r1, unsigned addr) {
    asm volatile("ldmatrix.sync.aligned.m8n8.x2.trans.shared.b16 {%0,%1}, [%2];"
                 : "=r"(r0), "=r"(r1) : "r"(addr));
}
__device__ __forceinline__ void mma16816(float* d, const unsigned* a,
                                         unsigned b0, unsigned b1) {
    asm volatile(
        "mma.sync.aligned.m16n8k16.row.col.f32.bf16.bf16.f32 "
        "{%0,%1,%2,%3}, {%4,%5,%6,%7}, {%8,%9}, {%0,%1,%2,%3};"
        : "+f"(d[0]), "+f"(d[1]), "+f"(d[2]), "+f"(d[3])
        : "r"(a[0]), "r"(a[1]), "r"(a[2]), "r"(a[3]), "r"(b0), "r"(b1));
}

// ---- dummy no-op kernel: shifts the ncu -s window onto kB ----
__global__ void kNop() {}

// ============================================================================
// Kernel A (HMMA): IW/IM = impact @ {W,M}.T -> e5m2 tables.   (unchanged R12)
// ============================================================================
#define KA_STR 136
#define SMEM_A (3 * 128 * KA_STR * 2 + 16)

__global__ void __launch_bounds__(256) kA(const float* __restrict__ impact,
                                          const float* __restrict__ W,
                                          const float* __restrict__ M,
                                          const float* __restrict__ W1) {
    extern __shared__ __half smh[];
    __half* sA = smh;                    // [128][KA_STR]
    __half* sW = smh + 128 * KA_STR;
    __half* sM = sW + 128 * KA_STR;

    const int tid = threadIdx.x;
    const int warp = tid >> 5, lane = tid & 31;
    const int rowBase = blockIdx.x * 128;

    if (blockIdx.x < 16) {
        const int base = blockIdx.x * 2048;
        for (int q = tid; q < 1024; q += 256) {
            const float2 v = *(const float2*)(W1 + base + (q << 1));
            *(__half2*)(g_W1h + base + (q << 1)) = __floats2half2_rn(v.x, v.y);
        }
    }

    for (int idx = tid; idx < 128 * 64; idx += 256) {
        const int r = idx >> 6, cp = (idx & 63) << 1;
        const int grow = rowBase + r;
        const float2 av = (grow < NTYPES) ? *(const float2*)(impact + (size_t)grow * 128 + cp)
                                          : make_float2(0.f, 0.f);
        const float2 wv = *(const float2*)(W + r * 128 + cp);
        const float2 mv = *(const float2*)(M + r * 128 + cp);
        *(__nv_bfloat162*)(sA + r * KA_STR + cp) = __floats2bfloat162_rn(av.x, av.y);
        *(__nv_bfloat162*)(sW + r * KA_STR + cp) = __floats2bfloat162_rn(wv.x, wv.y);
        *(__nv_bfloat162*)(sM + r * KA_STR + cp) = __floats2bfloat162_rn(mv.x, mv.y);
    }
    __syncthreads();

    const unsigned sbase = smem_u32(smh);
    const int wrb = warp << 4;

    const int aRow = wrb + (lane & 15);
    const unsigned aBase = sbase + ((unsigned)(aRow * KA_STR + ((lane >> 4) << 3)) << 1);
    unsigned a[8][4];
#pragma unroll
    for (int k = 0; k < 8; ++k)
        ldsm_x4(a[k][0], a[k][1], a[k][2], a[k][3], aBase + (k << 5));

    const unsigned bOff = ((unsigned)((lane & 7) * KA_STR + (((lane >> 3) & 1) << 3)) << 1);
    const unsigned wB = sbase + 128 * KA_STR * 2 + bOff;
    const unsigned mB = sbase + 2 * 128 * KA_STR * 2 + bOff;

    const int r0g = rowBase + wrb + (lane >> 2);
    const int r1g = r0g + 8;
    const int cbase = (lane & 3) << 1;

#pragma unroll
    for (int t = 0; t < 2; ++t) {
        const unsigned bb = t ? mB : wB;
        unsigned char* dst = t ? g_IM8 : g_IW8;
        float acc[16][4];
#pragma unroll
        for (int n = 0; n < 16; ++n) {
            acc[n][0] = acc[n][1] = acc[n][2] = acc[n][3] = 0.f;
        }
#pragma unroll
        for (int n = 0; n < 16; ++n) {
            const unsigned bn = bb + (unsigned)(n * 8 * KA_STR * 2);
#pragma unroll
            for (int k = 0; k < 8; ++k) {
                unsigned b0, b1;
                ldsm_x2t(b0, b1, bn + (k << 5));
                mma16816(acc[n], a[k], b0, b1);
            }
        }
#pragma unroll
        for (int n = 0; n < 16; ++n) {
            const unsigned short u0 = f2_to_e5m2x2(acc[n][0], acc[n][1]);
            const unsigned short u1 = f2_to_e5m2x2(acc[n][2], acc[n][3]);
            const int col = (n << 3) + cbase;
            if (r0g < NTYPES) *(unsigned short*)(dst + (size_t)r0g * 128 + col) = u0;
            if (r1g < NTYPES) *(unsigned short*)(dst + (size_t)r1g * 128 + col) = u1;
        }
    }
}

// ============================================================================
// Kernel B: per_graph gather-sum + softmax -> E.  (R12 form)
// ============================================================================
__global__ void __launch_bounds__(256) kB(const int* __restrict__ node_type,
                                          const int* __restrict__ nbr_type) {
    __shared__ int   sNT[64];
    __shared__ int   sNB[512];
    __shared__ float sP[8][132];
    __shared__ float sredm[8];
    __shared__ float sreds[8];

    const int tid = threadIdx.x;
    const int g = blockIdx.x;
    const int w = tid >> 5, lane = tid & 31;

    if (tid < 64) sNT[tid] = node_type[g * 64 + tid];
    for (int idx = tid; idx < 512; idx += 256) sNB[idx] = nbr_type[g * 512 + idx];
    __syncthreads();

    const int co = lane << 2;
    float4 acc = make_float4(0.f, 0.f, 0.f, 0.f);
#pragma unroll 2
    for (int kk = 0; kk < 8; ++kk) {
        const int k = (kk << 3) + w;
        const unsigned u = *(const unsigned*)(g_IW8 + (size_t)sNT[k] * 128 + co);
        unsigned p01 = E5M2_LO(u);
        unsigned p23 = E5M2_HI(u);
        __half2 s01 = *(__half2*)&p01;
        __half2 s23 = *(__half2*)&p23;
        const int* nbp = &sNB[k << 3];
#pragma unroll
        for (int d = 0; d < 8; ++d) {
            const unsigned v = *(const unsigned*)(g_IM8 + (size_t)nbp[d] * 128 + co);
            unsigned q01 = E5M2_LO(v);
            unsigned q23 = E5M2_HI(v);
            s01 = __hadd2(s01, *(__half2*)&q01);
            s23 = __hadd2(s23, *(__half2*)&q23);
        }
        const float2 f01 = __half22float2(s01);
        const float2 f23 = __half22float2(s23);
        acc.x += fmaxf(f01.x, 0.f);
        acc.y += fmaxf(f01.y, 0.f);
        acc.z += fmaxf(f23.x, 0.f);
        acc.w += fmaxf(f23.y, 0.f);
    }
    *(float4*)(&sP[w][co]) = acc;
    __syncthreads();

    float v = 0.f;
    if (tid < 128) {
#pragma unroll
        for (int ww = 0; ww < 8; ++ww) v += sP[ww][tid];
    }
    float m = v;
#pragma unroll
    for (int off = 16; off; off >>= 1)
        m = fmaxf(m, __shfl_xor_sync(0xffffffffu, m, off));
    if (lane == 0) sredm[w] = m;
    __syncthreads();
    const float M = fmaxf(fmaxf(sredm[0], sredm[1]), fmaxf(sredm[2], sredm[3]));

    const float e = (tid < 128) ? expf(v - M) : 0.f;
    float s = e;
#pragma unroll
    for (int off = 16; off; off >>= 1)
        s += __shfl_xor_sync(0xffffffffu, s, off);
    if (lane == 0) sreds[w] = s;
    __syncthreads();
    const float tot = sreds[0] + sreds[1] + sreds[2] + sreds[3];

    if (tid < 128) g_E[g * 128 + tid] = e / tot;
}

// ============================================================================
// Kernel C: ext = E @ U.T + Esum @ V.T ;  X = softmax(relu(ext))   (R12 form)
// ============================================================================
#define C_WSTR 132
#define C_ASTR 36
#define SMEM_C ((2 * 128 * C_WSTR + 2 * 128 * C_ASTR) * 4 + 512 * 4)

__global__ void __launch_bounds__(256) kC(const float* __restrict__ U,
                                          const float* __restrict__ V,
                                          const int* __restrict__ ext_nbr) {
    extern __shared__ float sm[];
    float* sUt = sm;
    float* sVt = sUt + 128 * C_WSTR;
    float* sEt = sVt + 128 * C_WSTR;
    float* sSt = sEt + 128 * C_ASTR;
    int*   sXN = (int*)(sSt + 128 * C_ASTR);

    const int tid = threadIdx.x;
    const int rowBase = blockIdx.x * 32;

    for (int idx = tid; idx < 128 * 128; idx += 256) {
        int j = idx >> 7, i = idx & 127;
        sUt[i * C_WSTR + j] = U[idx];
        sVt[i * C_WSTR + j] = V[idx];
    }
    for (int idx = tid; idx < 32 * 128; idx += 256) {
        int r = idx >> 7, i = idx & 127;
        int row = rowBase + r;
        sEt[i * C_ASTR + r] = (row < NG) ? g_E[row * 128 + i] : 0.f;
    }
    for (int idx = tid; idx < 512; idx += 256) {
        int row = rowBase + (idx >> 4);
        sXN[idx] = (row < NG) ? ext_nbr[row * 16 + (idx & 15)] : 0;
    }
    __syncthreads();

    for (int idx = tid; idx < 32 * 32; idx += 256) {
        int r = idx >> 5, c4 = (idx & 31) << 2;
        const int* xn = &sXN[r * 16];
        float4 s = make_float4(0.f, 0.f, 0.f, 0.f);
#pragma unroll
        for (int d = 0; d < 16; ++d) {
            const float4 v = *(const float4*)(g_E + xn[d] * 128 + c4);
            s.x += v.x; s.y += v.y; s.z += v.z; s.w += v.w;
        }
        sSt[(c4 + 0) * C_ASTR + r] = s.x;
        sSt[(c4 + 1) * C_ASTR + r] = s.y;
        sSt[(c4 + 2) * C_ASTR + r] = s.z;
        sSt[(c4 + 3) * C_ASTR + r] = s.w;
    }
    __syncthreads();

    const int tx = tid & 31;
    const int ty = tid >> 5;
    u64t acc2[2][4] = {};

#pragma unroll 4
    for (int i = 0; i < 128; ++i) {
        const float4 uv = *(const float4*)(sUt + i * C_WSTR + (tx << 2));
        const float4 vv = *(const float4*)(sVt + i * C_WSTR + (tx << 2));
        const float4 ev = *(const float4*)(sEt + i * C_ASTR + (ty << 2));
        const float4 qv = *(const float4*)(sSt + i * C_ASTR + (ty << 2));
        u64t ep[2], sp[2], ud[4], vd[4];
        ep[0] = pk2(ev.x, ev.y); ep[1] = pk2(ev.z, ev.w);
        sp[0] = pk2(qv.x, qv.y); sp[1] = pk2(qv.z, qv.w);
        ud[0] = pk2(uv.x, uv.x); ud[1] = pk2(uv.y, uv.y);
        ud[2] = pk2(uv.z, uv.z); ud[3] = pk2(uv.w, uv.w);
        vd[0] = pk2(vv.x, vv.x); vd[1] = pk2(vv.y, vv.y);
        vd[2] = pk2(vv.z, vv.z); vd[3] = pk2(vv.w, vv.w);
#pragma unroll
        for (int rp = 0; rp < 2; ++rp) {
#pragma unroll
            for (int cc = 0; cc < 4; ++cc) {
                FMA2(acc2[rp][cc], ep[rp], ud[cc]);
                FMA2(acc2[rp][cc], sp[rp], vd[cc]);
            }
        }
    }

#pragma unroll
    for (int rp = 0; rp < 2; ++rp) {
        const float2 c0 = upk2(acc2[rp][0]);
        const float2 c1 = upk2(acc2[rp][1]);
        const float2 c2 = upk2(acc2[rp][2]);
        const float2 c3 = upk2(acc2[rp][3]);
#pragma unroll
        for (int h = 0; h < 2; ++h) {
            const int row = rowBase + (ty << 2) + (rp << 1) + h;
            float v0 = fmaxf(h ? c0.y : c0.x, 0.f);
            float v1 = fmaxf(h ? c1.y : c1.x, 0.f);
            float v2 = fmaxf(h ? c2.y : c2.x, 0.f);
            float v3 = fmaxf(h ? c3.y : c3.x, 0.f);
            float m = fmaxf(fmaxf(v0, v1), fmaxf(v2, v3));
#pragma unroll
            for (int off = 16; off; off >>= 1)
                m = fmaxf(m, __shfl_xor_sync(0xffffffffu, m, off));
            float e0 = expf(v0 - m), e1 = expf(v1 - m), e2 = expf(v2 - m), e3 = expf(v3 - m);
            float s = e0 + e1 + e2 + e3;
#pragma unroll
            for (int off = 16; off; off >>= 1)
                s += __shfl_xor_sync(0xffffffffu, s, off);
            if (row < NG) {
                const float inv = 1.f / s;
                float4 o = make_float4(e0 * inv, e1 * inv, e2 * inv, e3 * inv);
                *(float4*)(g_X + row * 128 + (tx << 2)) = o;
            }
        }
    }
}

// ============================================================================
// Kernel D: ONE WAVE. 128 blocks x 8 rows; 512 threads; cp.async fill. (unchanged)
// ============================================================================
#define D2_STR 264
#define SMEM_D (128 * D2_STR * 2)

__global__ void __launch_bounds__(512) kD(const int* __restrict__ batch,
                                          const float* __restrict__ b1,
                                          const float* __restrict__ W2,
                                          const float* __restrict__ b2,
                                          float* __restrict__ out) {
    extern __shared__ __half sWh[];      // [128][D2_STR]
    __shared__ float sF[8][260];
    __shared__ float sW2[256];
    __shared__ float sB1[128];
    __shared__ float sP[16][2][2];

    const int tid = threadIdx.x;
    const int rg = tid >> 7;
    const int j = tid & 127;
    const int warp = tid >> 5, lane = tid & 31;

    const unsigned sbase = (unsigned)__cvta_generic_to_shared(sWh);
    for (int q = tid; q < 128 * 32; q += 512) {
        const int jr = q >> 5, i8 = (q & 31) << 3;
        cpa16(sbase + (jr * D2_STR + i8) * 2, g_W1h + (q << 3));
    }
    asm volatile("cp.async.commit_group;" ::: "memory");

    if (tid < 256) sW2[tid] = W2[tid];
    if (tid < 128) sB1[tid] = b1[tid];
    const float bb0 = b2[0], bb1 = b2[1];

    const int rb = rg << 1;
#pragma unroll
    for (int rr = 0; rr < 2; ++rr) {
        const int row = blockIdx.x * 8 + rb + rr;
        const int b0i = batch[2 * row];
        const int b1i = batch[2 * row + 1];
        const float e1 = g_X[b0i * 128 + j];
        const float e2 = g_X[b1i * 128 + j];
        sF[rb + rr][j] = e1 * e2;
        sF[rb + rr][128 + j] = e1 + e2;
    }
    asm volatile("cp.async.wait_group 0;" ::: "memory");
    __syncthreads();

    float4 a0 = make_float4(0.f, 0.f, 0.f, 0.f);
    float4 a1 = a0;
    const __half* wrow = sWh + j * D2_STR;
#pragma unroll 4
    for (int m = 0; m < 32; ++m) {
        const uint4 wv = *(const uint4*)(wrow + (m << 3));
        const float2 w01 = __half22float2(*(const __half2*)&wv.x);
        const float2 w23 = __half22float2(*(const __half2*)&wv.y);
        const float2 w45 = __half22float2(*(const __half2*)&wv.z);
        const float2 w67 = __half22float2(*(const __half2*)&wv.w);
        const float4 f0a = *(const float4*)(&sF[rb + 0][m << 3]);
        const float4 f0b = *(const float4*)(&sF[rb + 0][(m << 3) + 4]);
        const float4 f1a = *(const float4*)(&sF[rb + 1][m << 3]);
        const float4 f1b = *(const float4*)(&sF[rb + 1][(m << 3) + 4]);
        a0.x = fmaf(f0a.x, w01.x, a0.x); a0.y = fmaf(f0a.y, w01.y, a0.y);
        a0.z = fmaf(f0a.z, w23.x, a0.z); a0.w = fmaf(f0a.w, w23.y, a0.w);
        a0.x = fmaf(f0b.x, w45.x, a0.x); a0.y = fmaf(f0b.y, w45.y, a0.y);
        a0.z = fmaf(f0b.z, w67.x, a0.z); a0.w = fmaf(f0b.w, w67.y, a0.w);
        a1.x = fmaf(f1a.x, w01.x, a1.x); a1.y = fmaf(f1a.y, w01.y, a1.y);
        a1.z = fmaf(f1a.z, w23.x, a1.z); a1.w = fmaf(f1a.w, w23.y, a1.w);
        a1.x = fmaf(f1b.x, w45.x, a1.x); a1.y = fmaf(f1b.y, w45.y, a1.y);
        a1.z = fmaf(f1b.z, w67.x, a1.z); a1.w = fmaf(f1b.w, w67.y, a1.w);
    }

    const float bj = sB1[j];
    const float w2a = sW2[j], w2b = sW2[128 + j];
    const float h0 = fmaxf((a0.x + a0.y) + (a0.z + a0.w) + bj, 0.f);
    const float h1 = fmaxf((a1.x + a1.y) + (a1.z + a1.w) + bj, 0.f);

    float p00 = h0 * w2a, p01 = h0 * w2b;
    float p10 = h1 * w2a, p11 = h1 * w2b;
#pragma unroll
    for (int off = 16; off; off >>= 1) {
        p00 += __shfl_xor_sync(0xffffffffu, p00, off);
        p01 += __shfl_xor_sync(0xffffffffu, p01, off);
        p10 += __shfl_xor_sync(0xffffffffu, p10, off);
        p11 += __shfl_xor_sync(0xffffffffu, p11, off);
    }
    if (lane == 0) {
        sP[warp][0][0] = p00; sP[warp][0][1] = p01;
        sP[warp][1][0] = p10; sP[warp][1][1] = p11;
    }
    __syncthreads();

    if (tid < 8) {
        const int r = tid;
        const int wbase = (r >> 1) << 2;
        const int lr = r & 1;
        const int row = blockIdx.x * 8 + r;
        float o0 = bb0, o1 = bb1;
#pragma unroll
        for (int w2 = 0; w2 < 4; ++w2) {
            o0 += sP[wbase + w2][lr][0];
            o1 += sP[wbase + w2][lr][1];
        }
        const float mm = fmaxf(o0, o1);
        const float z0 = expf(o0 - mm), z1 = expf(o1 - mm);
        const float inv = 1.f / (z0 + z1);
        out[row * 2]     = z0 * inv;
        out[row * 2 + 1] = z1 * inv;
    }
}

// ============================================================================
extern "C" void kernel_launch(void* const* d_in, const int* in_sizes, int n_in,
                              void* d_out, int out_size) {
    const int*   batch     = (const int*)d_in[0];
    const int*   node_type = (const int*)d_in[1];
    const int*   nbr_type  = (const int*)d_in[2];
    const int*   ext_nbr   = (const int*)d_in[3];
    const float* impact    = (const float*)d_in[4];
    const float* W         = (const float*)d_in[5];
    const float* M         = (const float*)d_in[6];
    const float* U         = (const float*)d_in[7];
    const float* V         = (const float*)d_in[8];
    const float* W1        = (const float*)d_in[9];
    const float* b1        = (const float*)d_in[10];
    const float* W2        = (const float*)d_in[11];
    const float* b2        = (const float*)d_in[12];
    float* out = (float*)d_out;

    cudaFuncSetAttribute(kA, cudaFuncAttributeMaxDynamicSharedMemorySize, SMEM_A);
    cudaFuncSetAttribute(kC, cudaFuncAttributeMaxDynamicSharedMemorySize, SMEM_C);
    cudaFuncSetAttribute(kD, cudaFuncAttributeMaxDynamicSharedMemorySize, SMEM_D);

    // diagnostic: shift ncu's -s window so launch #6 = kB
    kNop<<<1, 32>>>();
    kNop<<<1, 32>>>();

    kA<<<(NTYPES + 127) / 128, 256, SMEM_A>>>(impact, W, M, W1);
    kB<<<NG, 256>>>(node_type, nbr_type);
    kC<<<(NG + 31) / 32, 256, SMEM_C>>>(U, V, ext_nbr);
    kD<<<NB / 8, 512, SMEM_D>>>(batch, b1, W2, b2, out);
}

// round 15
// speedup vs baseline: 1.0390x; 1.0114x over previous
#include <cuda_runtime.h>
#include <cuda_fp16.h>
#include <cuda_bf16.h>
#include <stdint.h>
#include <math.h>

#define NTYPES 10000
#define NG     2000
#define NB     1024

// ---------------- scratch (device globals) ----------------
__device__ __half g_IWh[NTYPES * 128];   // impact @ W.T  (fp16)
__device__ __half g_IMh[NTYPES * 128];   // impact @ M.T  (fp16)
__device__ __half g_W1h[128 * 256];      // W1 in fp16
__device__ float  g_E [NG * 128];        // softmax(per_graph)
__device__ float  g_X [NG * 128];        // softmax(relu(ext))

typedef unsigned long long u64t;
__device__ __forceinline__ u64t pk2(float lo, float hi) {
    u64t r;
    asm("mov.b64 %0, {%1, %2};" : "=l"(r) : "r"(__float_as_uint(lo)), "r"(__float_as_uint(hi)));
    return r;
}
__device__ __forceinline__ float2 upk2(u64t v) {
    unsigned lo, hi;
    asm("mov.b64 {%0, %1}, %2;" : "=r"(lo), "=r"(hi) : "l"(v));
    return make_float2(__uint_as_float(lo), __uint_as_float(hi));
}
#define FMA2(d, a, b) asm("fma.rn.f32x2 %0, %1, %2, %0;" : "+l"(d) : "l"(a), "l"(b))

__device__ __forceinline__ void cpa16(unsigned daddr, const void* src) {
    asm volatile("cp.async.cg.shared.global [%0], [%1], 16;" :: "r"(daddr), "l"(src));
}
__device__ __forceinline__ unsigned smem_u32(const void* p) {
    unsigned a;
    asm("{ .reg .u64 t; cvta.to.shared.u64 t, %1; cvt.u32.u64 %0, t; }" : "=r"(a) : "l"(p));
    return a;
}

// ---------------- mma.sync (sm_80+, legal on base sm_103 target) ------------
__device__ __forceinline__ void ldsm_x4(unsigned& r0, unsigned& r1,
                                        unsigned& r2, unsigned& r3, unsigned addr) {
    asm volatile("ldmatrix.sync.aligned.m8n8.x4.shared.b16 {%0,%1,%2,%3}, [%4];"
                 : "=r"(r0), "=r"(r1), "=r"(r2), "=r"(r3) : "r"(addr));
}
__device__ __forceinline__ void ldsm_x2t(unsigned& r0, unsigned& r1, unsigned addr) {
    asm volatile("ldmatrix.sync.aligned.m8n8.x2.trans.shared.b16 {%0,%1}, [%2];"
                 : "=r"(r0), "=r"(r1) : "r"(addr));
}
__device__ __forceinline__ void mma16816(float* d, const unsigned* a,
                                         unsigned b0, unsigned b1) {
    asm volatile(
        "mma.sync.aligned.m16n8k16.row.col.f32.bf16.bf16.f32 "
        "{%0,%1,%2,%3}, {%4,%5,%6,%7}, {%8,%9}, {%0,%1,%2,%3};"
        : "+f"(d[0]), "+f"(d[1]), "+f"(d[2]), "+f"(d[3])
        : "r"(a[0]), "r"(a[1]), "r"(a[2]), "r"(a[3]), "r"(b0), "r"(b1));
}

// ---- dummy no-op kernel: shifts the ncu -s window (this round -> kC) ----
__global__ void kNop() {}

// ============================================================================
// Kernel A (HMMA): IW/IM = impact @ {W,M}.T -> fp16 tables.
// 79 blocks x 128 rows; 256 threads (8 warps x 16 rows).
// ============================================================================
#define KA_STR 136
#define SMEM_A (3 * 128 * KA_STR * 2 + 16)

__global__ void __launch_bounds__(256) kA(const float* __restrict__ impact,
                                          const float* __restrict__ W,
                                          const float* __restrict__ M,
                                          const float* __restrict__ W1) {
    extern __shared__ __half smh[];
    __half* sA = smh;                    // [128][KA_STR]
    __half* sW = smh + 128 * KA_STR;
    __half* sM = sW + 128 * KA_STR;

    const int tid = threadIdx.x;
    const int warp = tid >> 5, lane = tid & 31;
    const int rowBase = blockIdx.x * 128;

    if (blockIdx.x < 16) {
        const int base = blockIdx.x * 2048;
        for (int q = tid; q < 1024; q += 256) {
            const float2 v = *(const float2*)(W1 + base + (q << 1));
            *(__half2*)(g_W1h + base + (q << 1)) = __floats2half2_rn(v.x, v.y);
        }
    }

    for (int idx = tid; idx < 128 * 64; idx += 256) {
        const int r = idx >> 6, cp = (idx & 63) << 1;
        const int grow = rowBase + r;
        const float2 av = (grow < NTYPES) ? *(const float2*)(impact + (size_t)grow * 128 + cp)
                                          : make_float2(0.f, 0.f);
        const float2 wv = *(const float2*)(W + r * 128 + cp);
        const float2 mv = *(const float2*)(M + r * 128 + cp);
        *(__nv_bfloat162*)(sA + r * KA_STR + cp) = __floats2bfloat162_rn(av.x, av.y);
        *(__nv_bfloat162*)(sW + r * KA_STR + cp) = __floats2bfloat162_rn(wv.x, wv.y);
        *(__nv_bfloat162*)(sM + r * KA_STR + cp) = __floats2bfloat162_rn(mv.x, mv.y);
    }
    __syncthreads();

    const unsigned sbase = smem_u32(smh);
    const int wrb = warp << 4;

    const int aRow = wrb + (lane & 15);
    const unsigned aBase = sbase + ((unsigned)(aRow * KA_STR + ((lane >> 4) << 3)) << 1);
    unsigned a[8][4];
#pragma unroll
    for (int k = 0; k < 8; ++k)
        ldsm_x4(a[k][0], a[k][1], a[k][2], a[k][3], aBase + (k << 5));

    const unsigned bOff = ((unsigned)((lane & 7) * KA_STR + (((lane >> 3) & 1) << 3)) << 1);
    const unsigned wB = sbase + 128 * KA_STR * 2 + bOff;
    const unsigned mB = sbase + 2 * 128 * KA_STR * 2 + bOff;

    const int r0g = rowBase + wrb + (lane >> 2);
    const int r1g = r0g + 8;
    const int cbase = (lane & 3) << 1;

#pragma unroll
    for (int t = 0; t < 2; ++t) {
        const unsigned bb = t ? mB : wB;
        __half* dst = t ? g_IMh : g_IWh;
        float acc[16][4];
#pragma unroll
        for (int n = 0; n < 16; ++n) {
            acc[n][0] = acc[n][1] = acc[n][2] = acc[n][3] = 0.f;
        }
#pragma unroll
        for (int n = 0; n < 16; ++n) {
            const unsigned bn = bb + (unsigned)(n * 8 * KA_STR * 2);
#pragma unroll
            for (int k = 0; k < 8; ++k) {
                unsigned b0, b1;
                ldsm_x2t(b0, b1, bn + (k << 5));
                mma16816(acc[n], a[k], b0, b1);
            }
        }
#pragma unroll
        for (int n = 0; n < 16; ++n) {
            const __half2 h0 = __floats2half2_rn(acc[n][0], acc[n][1]);
            const __half2 h1 = __floats2half2_rn(acc[n][2], acc[n][3]);
            const int col = (n << 3) + cbase;
            if (r0g < NTYPES) *(__half2*)(dst + (size_t)r0g * 128 + col) = h0;
            if (r1g < NTYPES) *(__half2*)(dst + (size_t)r1g * 128 + col) = h1;
        }
    }
}

// ============================================================================
// Kernel B: per_graph gather-sum + softmax -> E.
// fp16 tables, LDG.64 gathers, pure half2 accumulate (zero unpack ALU).
// ============================================================================
__global__ void __launch_bounds__(256) kB(const int* __restrict__ node_type,
                                          const int* __restrict__ nbr_type) {
    __shared__ int   sNT[64];
    __shared__ int   sNB[512];
    __shared__ float sP[8][132];
    __shared__ float sredm[8];
    __shared__ float sreds[8];

    const int tid = threadIdx.x;
    const int g = blockIdx.x;
    const int w = tid >> 5, lane = tid & 31;

    if (tid < 64) sNT[tid] = node_type[g * 64 + tid];
    for (int idx = tid; idx < 512; idx += 256) sNB[idx] = nbr_type[g * 512 + idx];
    __syncthreads();

    const int co = lane << 2;   // 4 halves per lane
    float4 acc = make_float4(0.f, 0.f, 0.f, 0.f);
#pragma unroll 2
    for (int kk = 0; kk < 8; ++kk) {
        const int k = (kk << 3) + w;
        const uint2 u = *(const uint2*)(g_IWh + (size_t)sNT[k] * 128 + co);
        __half2 s01 = *(__half2*)&u.x;
        __half2 s23 = *(__half2*)&u.y;
        const int* nbp = &sNB[k << 3];
#pragma unroll
        for (int d = 0; d < 8; ++d) {
            const uint2 v = *(const uint2*)(g_IMh + (size_t)nbp[d] * 128 + co);
            s01 = __hadd2(s01, *(__half2*)&v.x);
            s23 = __hadd2(s23, *(__half2*)&v.y);
        }
        const float2 f01 = __half22float2(s01);
        const float2 f23 = __half22float2(s23);
        acc.x += fmaxf(f01.x, 0.f);
        acc.y += fmaxf(f01.y, 0.f);
        acc.z += fmaxf(f23.x, 0.f);
        acc.w += fmaxf(f23.y, 0.f);
    }
    *(float4*)(&sP[w][co]) = acc;
    __syncthreads();

    float v = 0.f;
    if (tid < 128) {
#pragma unroll
        for (int ww = 0; ww < 8; ++ww) v += sP[ww][tid];
    }
    float m = v;
#pragma unroll
    for (int off = 16; off; off >>= 1)
        m = fmaxf(m, __shfl_xor_sync(0xffffffffu, m, off));
    if (lane == 0) sredm[w] = m;
    __syncthreads();
    const float M = fmaxf(fmaxf(sredm[0], sredm[1]), fmaxf(sredm[2], sredm[3]));

    const float e = (tid < 128) ? expf(v - M) : 0.f;
    float s = e;
#pragma unroll
    for (int off = 16; off; off >>= 1)
        s += __shfl_xor_sync(0xffffffffu, s, off);
    if (lane == 0) sreds[w] = s;
    __syncthreads();
    const float tot = sreds[0] + sreds[1] + sreds[2] + sreds[3];

    if (tid < 128) g_E[g * 128 + tid] = e / tot;
}

// ============================================================================
// Kernel C: ext = E @ U.T + Esum @ V.T ;  X = softmax(relu(ext))   (R12 form)
// ============================================================================
#define C_WSTR 132
#define C_ASTR 36
#define SMEM_C ((2 * 128 * C_WSTR + 2 * 128 * C_ASTR) * 4 + 512 * 4)

__global__ void __launch_bounds__(256) kC(const float* __restrict__ U,
                                          const float* __restrict__ V,
                                          const int* __restrict__ ext_nbr) {
    extern __shared__ float sm[];
    float* sUt = sm;
    float* sVt = sUt + 128 * C_WSTR;
    float* sEt = sVt + 128 * C_WSTR;
    float* sSt = sEt + 128 * C_ASTR;
    int*   sXN = (int*)(sSt + 128 * C_ASTR);

    const int tid = threadIdx.x;
    const int rowBase = blockIdx.x * 32;

    for (int idx = tid; idx < 128 * 128; idx += 256) {
        int j = idx >> 7, i = idx & 127;
        sUt[i * C_WSTR + j] = U[idx];
        sVt[i * C_WSTR + j] = V[idx];
    }
    for (int idx = tid; idx < 32 * 128; idx += 256) {
        int r = idx >> 7, i = idx & 127;
        int row = rowBase + r;
        sEt[i * C_ASTR + r] = (row < NG) ? g_E[row * 128 + i] : 0.f;
    }
    for (int idx = tid; idx < 512; idx += 256) {
        int row = rowBase + (idx >> 4);
        sXN[idx] = (row < NG) ? ext_nbr[row * 16 + (idx & 15)] : 0;
    }
    __syncthreads();

    for (int idx = tid; idx < 32 * 32; idx += 256) {
        int r = idx >> 5, c4 = (idx & 31) << 2;
        const int* xn = &sXN[r * 16];
        float4 s = make_float4(0.f, 0.f, 0.f, 0.f);
#pragma unroll
        for (int d = 0; d < 16; ++d) {
            const float4 v = *(const float4*)(g_E + xn[d] * 128 + c4);
            s.x += v.x; s.y += v.y; s.z += v.z; s.w += v.w;
        }
        sSt[(c4 + 0) * C_ASTR + r] = s.x;
        sSt[(c4 + 1) * C_ASTR + r] = s.y;
        sSt[(c4 + 2) * C_ASTR + r] = s.z;
        sSt[(c4 + 3) * C_ASTR + r] = s.w;
    }
    __syncthreads();

    const int tx = tid & 31;
    const int ty = tid >> 5;
    u64t acc2[2][4] = {};

#pragma unroll 4
    for (int i = 0; i < 128; ++i) {
        const float4 uv = *(const float4*)(sUt + i * C_WSTR + (tx << 2));
        const float4 vv = *(const float4*)(sVt + i * C_WSTR + (tx << 2));
        const float4 ev = *(const float4*)(sEt + i * C_ASTR + (ty << 2));
        const float4 qv = *(const float4*)(sSt + i * C_ASTR + (ty << 2));
        u64t ep[2], sp[2], ud[4], vd[4];
        ep[0] = pk2(ev.x, ev.y); ep[1] = pk2(ev.z, ev.w);
        sp[0] = pk2(qv.x, qv.y); sp[1] = pk2(qv.z, qv.w);
        ud[0] = pk2(uv.x, uv.x); ud[1] = pk2(uv.y, uv.y);
        ud[2] = pk2(uv.z, uv.z); ud[3] = pk2(uv.w, uv.w);
        vd[0] = pk2(vv.x, vv.x); vd[1] = pk2(vv.y, vv.y);
        vd[2] = pk2(vv.z, vv.z); vd[3] = pk2(vv.w, vv.w);
#pragma unroll
        for (int rp = 0; rp < 2; ++rp) {
#pragma unroll
            for (int cc = 0; cc < 4; ++cc) {
                FMA2(acc2[rp][cc], ep[rp], ud[cc]);
                FMA2(acc2[rp][cc], sp[rp], vd[cc]);
            }
        }
    }

#pragma unroll
    for (int rp = 0; rp < 2; ++rp) {
        const float2 c0 = upk2(acc2[rp][0]);
        const float2 c1 = upk2(acc2[rp][1]);
        const float2 c2 = upk2(acc2[rp][2]);
        const float2 c3 = upk2(acc2[rp][3]);
#pragma unroll
        for (int h = 0; h < 2; ++h) {
            const int row = rowBase + (ty << 2) + (rp << 1) + h;
            float v0 = fmaxf(h ? c0.y : c0.x, 0.f);
            float v1 = fmaxf(h ? c1.y : c1.x, 0.f);
            float v2 = fmaxf(h ? c2.y : c2.x, 0.f);
            float v3 = fmaxf(h ? c3.y : c3.x, 0.f);
            float m = fmaxf(fmaxf(v0, v1), fmaxf(v2, v3));
#pragma unroll
            for (int off = 16; off; off >>= 1)
                m = fmaxf(m, __shfl_xor_sync(0xffffffffu, m, off));
            float e0 = expf(v0 - m), e1 = expf(v1 - m), e2 = expf(v2 - m), e3 = expf(v3 - m);
            float s = e0 + e1 + e2 + e3;
#pragma unroll
            for (int off = 16; off; off >>= 1)
                s += __shfl_xor_sync(0xffffffffu, s, off);
            if (row < NG) {
                const float inv = 1.f / s;
                float4 o = make_float4(e0 * inv, e1 * inv, e2 * inv, e3 * inv);
                *(float4*)(g_X + row * 128 + (tx << 2)) = o;
            }
        }
    }
}

// ============================================================================
// Kernel D: ONE WAVE. 128 blocks x 8 rows; 512 threads; cp.async fill. (unchanged)
// ============================================================================
#define D2_STR 264
#define SMEM_D (128 * D2_STR * 2)

__global__ void __launch_bounds__(512) kD(const int* __restrict__ batch,
                                          const float* __restrict__ b1,
                                          const float* __restrict__ W2,
                                          const float* __restrict__ b2,
                                          float* __restrict__ out) {
    extern __shared__ __half sWh[];      // [128][D2_STR]
    __shared__ float sF[8][260];
    __shared__ float sW2[256];
    __shared__ float sB1[128];
    __shared__ float sP[16][2][2];

    const int tid = threadIdx.x;
    const int rg = tid >> 7;
    const int j = tid & 127;
    const int warp = tid >> 5, lane = tid & 31;

    const unsigned sbase = (unsigned)__cvta_generic_to_shared(sWh);
    for (int q = tid; q < 128 * 32; q += 512) {
        const int jr = q >> 5, i8 = (q & 31) << 3;
        cpa16(sbase + (jr * D2_STR + i8) * 2, g_W1h + (q << 3));
    }
    asm volatile("cp.async.commit_group;" ::: "memory");

    if (tid < 256) sW2[tid] = W2[tid];
    if (tid < 128) sB1[tid] = b1[tid];
    const float bb0 = b2[0], bb1 = b2[1];

    const int rb = rg << 1;
#pragma unroll
    for (int rr = 0; rr < 2; ++rr) {
        const int row = blockIdx.x * 8 + rb + rr;
        const int b0i = batch[2 * row];
        const int b1i = batch[2 * row + 1];
        const float e1 = g_X[b0i * 128 + j];
        const float e2 = g_X[b1i * 128 + j];
        sF[rb + rr][j] = e1 * e2;
        sF[rb + rr][128 + j] = e1 + e2;
    }
    asm volatile("cp.async.wait_group 0;" ::: "memory");
    __syncthreads();

    float4 a0 = make_float4(0.f, 0.f, 0.f, 0.f);
    float4 a1 = a0;
    const __half* wrow = sWh + j * D2_STR;
#pragma unroll 4
    for (int m = 0; m < 32; ++m) {
        const uint4 wv = *(const uint4*)(wrow + (m << 3));
        const float2 w01 = __half22float2(*(const __half2*)&wv.x);
        const float2 w23 = __half22float2(*(const __half2*)&wv.y);
        const float2 w45 = __half22float2(*(const __half2*)&wv.z);
        const float2 w67 = __half22float2(*(const __half2*)&wv.w);
        const float4 f0a = *(const float4*)(&sF[rb + 0][m << 3]);
        const float4 f0b = *(const float4*)(&sF[rb + 0][(m << 3) + 4]);
        const float4 f1a = *(const float4*)(&sF[rb + 1][m << 3]);
        const float4 f1b = *(const float4*)(&sF[rb + 1][(m << 3) + 4]);
        a0.x = fmaf(f0a.x, w01.x, a0.x); a0.y = fmaf(f0a.y, w01.y, a0.y);
        a0.z = fmaf(f0a.z, w23.x, a0.z); a0.w = fmaf(f0a.w, w23.y, a0.w);
        a0.x = fmaf(f0b.x, w45.x, a0.x); a0.y = fmaf(f0b.y, w45.y, a0.y);
        a0.z = fmaf(f0b.z, w67.x, a0.z); a0.w = fmaf(f0b.w, w67.y, a0.w);
        a1.x = fmaf(f1a.x, w01.x, a1.x); a1.y = fmaf(f1a.y, w01.y, a1.y);
        a1.z = fmaf(f1a.z, w23.x, a1.z); a1.w = fmaf(f1a.w, w23.y, a1.w);
        a1.x = fmaf(f1b.x, w45.x, a1.x); a1.y = fmaf(f1b.y, w45.y, a1.y);
        a1.z = fmaf(f1b.z, w67.x, a1.z); a1.w = fmaf(f1b.w, w67.y, a1.w);
    }

    const float bj = sB1[j];
    const float w2a = sW2[j], w2b = sW2[128 + j];
    const float h0 = fmaxf((a0.x + a0.y) + (a0.z + a0.w) + bj, 0.f);
    const float h1 = fmaxf((a1.x + a1.y) + (a1.z + a1.w) + bj, 0.f);

    float p00 = h0 * w2a, p01 = h0 * w2b;
    float p10 = h1 * w2a, p11 = h1 * w2b;
#pragma unroll
    for (int off = 16; off; off >>= 1) {
        p00 += __shfl_xor_sync(0xffffffffu, p00, off);
        p01 += __shfl_xor_sync(0xffffffffu, p01, off);
        p10 += __shfl_xor_sync(0xffffffffu, p10, off);
        p11 += __shfl_xor_sync(0xffffffffu, p11, off);
    }
    if (lane == 0) {
        sP[warp][0][0] = p00; sP[warp][0][1] = p01;
        sP[warp][1][0] = p10; sP[warp][1][1] = p11;
    }
    __syncthreads();

    if (tid < 8) {
        const int r = tid;
        const int wbase = (r >> 1) << 2;
        const int lr = r & 1;
        const int row = blockIdx.x * 8 + r;
        float o0 = bb0, o1 = bb1;
#pragma unroll
        for (int w2 = 0; w2 < 4; ++w2) {
            o0 += sP[wbase + w2][lr][0];
            o1 += sP[wbase + w2][lr][1];
        }
        const float mm = fmaxf(o0, o1);
        const float z0 = expf(o0 - mm), z1 = expf(o1 - mm);
        const float inv = 1.f / (z0 + z1);
        out[row * 2]     = z0 * inv;
        out[row * 2 + 1] = z1 * inv;
    }
}

// ============================================================================
extern "C" void kernel_launch(void* const* d_in, const int* in_sizes, int n_in,
                              void* d_out, int out_size) {
    const int*   batch     = (const int*)d_in[0];
    const int*   node_type = (const int*)d_in[1];
    const int*   nbr_type  = (const int*)d_in[2];
    const int*   ext_nbr   = (const int*)d_in[3];
    const float* impact    = (const float*)d_in[4];
    const float* W         = (const float*)d_in[5];
    const float* M         = (const float*)d_in[6];
    const float* U         = (const float*)d_in[7];
    const float* V         = (const float*)d_in[8];
    const float* W1        = (const float*)d_in[9];
    const float* b1        = (const float*)d_in[10];
    const float* W2        = (const float*)d_in[11];
    const float* b2        = (const float*)d_in[12];
    float* out = (float*)d_out;

    cudaFuncSetAttribute(kA, cudaFuncAttributeMaxDynamicSharedMemorySize, SMEM_A);
    cudaFuncSetAttribute(kC, cudaFuncAttributeMaxDynamicSharedMemorySize, SMEM_C);
    cudaFuncSetAttribute(kD, cudaFuncAttributeMaxDynamicSharedMemorySize, SMEM_D);

    // diagnostic: one dummy -> ncu's -s window lands on kC this round
    kNop<<<1, 32>>>();

    kA<<<(NTYPES + 127) / 128, 256, SMEM_A>>>(impact, W, M, W1);
    kB<<<NG, 256>>>(node_type, nbr_type);
    kC<<<(NG + 31) / 32, 256, SMEM_C>>>(U, V, ext_nbr);
    kD<<<NB / 8, 512, SMEM_D>>>(batch, b1, W2, b2, out);
}

// round 16
// speedup vs baseline: 1.0628x; 1.0229x over previous
#include <cuda_runtime.h>
#include <cuda_fp16.h>
#include <cuda_bf16.h>
#include <stdint.h>
#include <math.h>

#define NTYPES 10000
#define NG     2000
#define NB     1024

// ---------------- scratch (device globals) ----------------
__device__ __half g_IWh[NTYPES * 128];   // impact @ W.T  (fp16)
__device__ __half g_IMh[NTYPES * 128];   // impact @ M.T  (fp16)
__device__ __half g_W1h[128 * 256];      // W1 in fp16
__device__ float  g_E [NG * 128];        // softmax(per_graph)
__device__ float  g_X [NG * 128];        // softmax(relu(ext))

typedef unsigned long long u64t;
__device__ __forceinline__ u64t pk2(float lo, float hi) {
    u64t r;
    asm("mov.b64 %0, {%1, %2};" : "=l"(r) : "r"(__float_as_uint(lo)), "r"(__float_as_uint(hi)));
    return r;
}
__device__ __forceinline__ float2 upk2(u64t v) {
    unsigned lo, hi;
    asm("mov.b64 {%0, %1}, %2;" : "=r"(lo), "=r"(hi) : "l"(v));
    return make_float2(__uint_as_float(lo), __uint_as_float(hi));
}
#define FMA2(d, a, b) asm("fma.rn.f32x2 %0, %1, %2, %0;" : "+l"(d) : "l"(a), "l"(b))

__device__ __forceinline__ void cpa16(unsigned daddr, const void* src) {
    asm volatile("cp.async.cg.shared.global [%0], [%1], 16;" :: "r"(daddr), "l"(src));
}
__device__ __forceinline__ unsigned smem_u32(const void* p) {
    unsigned a;
    asm("{ .reg .u64 t; cvta.to.shared.u64 t, %1; cvt.u32.u64 %0, t; }" : "=r"(a) : "l"(p));
    return a;
}

// ---------------- mma.sync (sm_80+, legal on base sm_103 target) ------------
__device__ __forceinline__ void ldsm_x4(unsigned& r0, unsigned& r1,
                                        unsigned& r2, unsigned& r3, unsigned addr) {
    asm volatile("ldmatrix.sync.aligned.m8n8.x4.shared.b16 {%0,%1,%2,%3}, [%4];"
                 : "=r"(r0), "=r"(r1), "=r"(r2), "=r"(r3) : "r"(addr));
}
__device__ __forceinline__ void ldsm_x2t(unsigned& r0, unsigned& r1, unsigned addr) {
    asm volatile("ldmatrix.sync.aligned.m8n8.x2.trans.shared.b16 {%0,%1}, [%2];"
                 : "=r"(r0), "=r"(r1) : "r"(addr));
}
__device__ __forceinline__ void mma16816(float* d, const unsigned* a,
                                         unsigned b0, unsigned b1) {
    asm volatile(
        "mma.sync.aligned.m16n8k16.row.col.f32.bf16.bf16.f32 "
        "{%0,%1,%2,%3}, {%4,%5,%6,%7}, {%8,%9}, {%0,%1,%2,%3};"
        : "+f"(d[0]), "+f"(d[1]), "+f"(d[2]), "+f"(d[3])
        : "r"(a[0]), "r"(a[1]), "r"(a[2]), "r"(a[3]), "r"(b0), "r"(b1));
}

// ---- dummy no-op kernel: keeps ncu's -s window on kC ----
__global__ void kNop() {}

// ============================================================================
// Kernel A (HMMA): IW/IM = impact @ {W,M}.T -> fp16 tables.   (unchanged)
// ============================================================================
#define KA_STR 136
#define SMEM_A (3 * 128 * KA_STR * 2 + 16)

__global__ void __launch_bounds__(256) kA(const float* __restrict__ impact,
                                          const float* __restrict__ W,
                                          const float* __restrict__ M,
                                          const float* __restrict__ W1) {
    extern __shared__ __half smh[];
    __half* sA = smh;                    // [128][KA_STR]
    __half* sW = smh + 128 * KA_STR;
    __half* sM = sW + 128 * KA_STR;

    const int tid = threadIdx.x;
    const int warp = tid >> 5, lane = tid & 31;
    const int rowBase = blockIdx.x * 128;

    if (blockIdx.x < 16) {
        const int base = blockIdx.x * 2048;
        for (int q = tid; q < 1024; q += 256) {
            const float2 v = *(const float2*)(W1 + base + (q << 1));
            *(__half2*)(g_W1h + base + (q << 1)) = __floats2half2_rn(v.x, v.y);
        }
    }

    for (int idx = tid; idx < 128 * 64; idx += 256) {
        const int r = idx >> 6, cp = (idx & 63) << 1;
        const int grow = rowBase + r;
        const float2 av = (grow < NTYPES) ? *(const float2*)(impact + (size_t)grow * 128 + cp)
                                          : make_float2(0.f, 0.f);
        const float2 wv = *(const float2*)(W + r * 128 + cp);
        const float2 mv = *(const float2*)(M + r * 128 + cp);
        *(__nv_bfloat162*)(sA + r * KA_STR + cp) = __floats2bfloat162_rn(av.x, av.y);
        *(__nv_bfloat162*)(sW + r * KA_STR + cp) = __floats2bfloat162_rn(wv.x, wv.y);
        *(__nv_bfloat162*)(sM + r * KA_STR + cp) = __floats2bfloat162_rn(mv.x, mv.y);
    }
    __syncthreads();

    const unsigned sbase = smem_u32(smh);
    const int wrb = warp << 4;

    const int aRow = wrb + (lane & 15);
    const unsigned aBase = sbase + ((unsigned)(aRow * KA_STR + ((lane >> 4) << 3)) << 1);
    unsigned a[8][4];
#pragma unroll
    for (int k = 0; k < 8; ++k)
        ldsm_x4(a[k][0], a[k][1], a[k][2], a[k][3], aBase + (k << 5));

    const unsigned bOff = ((unsigned)((lane & 7) * KA_STR + (((lane >> 3) & 1) << 3)) << 1);
    const unsigned wB = sbase + 128 * KA_STR * 2 + bOff;
    const unsigned mB = sbase + 2 * 128 * KA_STR * 2 + bOff;

    const int r0g = rowBase + wrb + (lane >> 2);
    const int r1g = r0g + 8;
    const int cbase = (lane & 3) << 1;

#pragma unroll
    for (int t = 0; t < 2; ++t) {
        const unsigned bb = t ? mB : wB;
        __half* dst = t ? g_IMh : g_IWh;
        float acc[16][4];
#pragma unroll
        for (int n = 0; n < 16; ++n) {
            acc[n][0] = acc[n][1] = acc[n][2] = acc[n][3] = 0.f;
        }
#pragma unroll
        for (int n = 0; n < 16; ++n) {
            const unsigned bn = bb + (unsigned)(n * 8 * KA_STR * 2);
#pragma unroll
            for (int k = 0; k < 8; ++k) {
                unsigned b0, b1;
                ldsm_x2t(b0, b1, bn + (k << 5));
                mma16816(acc[n], a[k], b0, b1);
            }
        }
#pragma unroll
        for (int n = 0; n < 16; ++n) {
            const __half2 h0 = __floats2half2_rn(acc[n][0], acc[n][1]);
            const __half2 h1 = __floats2half2_rn(acc[n][2], acc[n][3]);
            const int col = (n << 3) + cbase;
            if (r0g < NTYPES) *(__half2*)(dst + (size_t)r0g * 128 + col) = h0;
            if (r1g < NTYPES) *(__half2*)(dst + (size_t)r1g * 128 + col) = h1;
        }
    }
}

// ============================================================================
// Kernel B: per_graph gather-sum + softmax -> E.  (unchanged R15)
// ============================================================================
__global__ void __launch_bounds__(256) kB(const int* __restrict__ node_type,
                                          const int* __restrict__ nbr_type) {
    __shared__ int   sNT[64];
    __shared__ int   sNB[512];
    __shared__ float sP[8][132];
    __shared__ float sredm[8];
    __shared__ float sreds[8];

    const int tid = threadIdx.x;
    const int g = blockIdx.x;
    const int w = tid >> 5, lane = tid & 31;

    if (tid < 64) sNT[tid] = node_type[g * 64 + tid];
    for (int idx = tid; idx < 512; idx += 256) sNB[idx] = nbr_type[g * 512 + idx];
    __syncthreads();

    const int co = lane << 2;   // 4 halves per lane
    float4 acc = make_float4(0.f, 0.f, 0.f, 0.f);
#pragma unroll 2
    for (int kk = 0; kk < 8; ++kk) {
        const int k = (kk << 3) + w;
        const uint2 u = *(const uint2*)(g_IWh + (size_t)sNT[k] * 128 + co);
        __half2 s01 = *(__half2*)&u.x;
        __half2 s23 = *(__half2*)&u.y;
        const int* nbp = &sNB[k << 3];
#pragma unroll
        for (int d = 0; d < 8; ++d) {
            const uint2 v = *(const uint2*)(g_IMh + (size_t)nbp[d] * 128 + co);
            s01 = __hadd2(s01, *(__half2*)&v.x);
            s23 = __hadd2(s23, *(__half2*)&v.y);
        }
        const float2 f01 = __half22float2(s01);
        const float2 f23 = __half22float2(s23);
        acc.x += fmaxf(f01.x, 0.f);
        acc.y += fmaxf(f01.y, 0.f);
        acc.z += fmaxf(f23.x, 0.f);
        acc.w += fmaxf(f23.y, 0.f);
    }
    *(float4*)(&sP[w][co]) = acc;
    __syncthreads();

    float v = 0.f;
    if (tid < 128) {
#pragma unroll
        for (int ww = 0; ww < 8; ++ww) v += sP[ww][tid];
    }
    float m = v;
#pragma unroll
    for (int off = 16; off; off >>= 1)
        m = fmaxf(m, __shfl_xor_sync(0xffffffffu, m, off));
    if (lane == 0) sredm[w] = m;
    __syncthreads();
    const float M = fmaxf(fmaxf(sredm[0], sredm[1]), fmaxf(sredm[2], sredm[3]));

    const float e = (tid < 128) ? expf(v - M) : 0.f;
    float s = e;
#pragma unroll
    for (int off = 16; off; off >>= 1)
        s += __shfl_xor_sync(0xffffffffu, s, off);
    if (lane == 0) sreds[w] = s;
    __syncthreads();
    const float tot = sreds[0] + sreds[1] + sreds[2] + sreds[3];

    if (tid < 128) g_E[g * 128 + tid] = e / tot;
}

// ============================================================================
// Kernel C: ext = E @ U.T + Esum @ V.T ;  X = softmax(relu(ext))
// ONE WAVE: 125 blocks x 16 rows.  Vectorized fills; 2 rows/thread GEMM.
// ============================================================================
#define C_WSTR 132
#define C_ASTR 18
#define C_ROWS 16
#define SMEM_C ((2 * 128 * C_WSTR + 2 * 128 * C_ASTR) * 4 + 256 * 4)

__global__ void __launch_bounds__(256) kC(const float* __restrict__ U,
                                          const float* __restrict__ V,
                                          const int* __restrict__ ext_nbr) {
    extern __shared__ float sm[];
    float* sUt = sm;                       // [128][C_WSTR]  Ut[i][j] = U[j][i]
    float* sVt = sUt + 128 * C_WSTR;
    float* sEt = sVt + 128 * C_WSTR;       // [128][C_ASTR]  E^T tile
    float* sSt = sEt + 128 * C_ASTR;       // [128][C_ASTR]  Esum^T tile
    int*   sXN = (int*)(sSt + 128 * C_ASTR);   // [16*16]

    const int tid = threadIdx.x;
    const int rowBase = blockIdx.x * C_ROWS;   // 125*16 = 2000 exact

    // U/V transposed fill, vectorized reads (float4), scalar scatter
    for (int idx = tid; idx < 128 * 32; idx += 256) {
        const int j = idx >> 5, i4 = (idx & 31) << 2;
        const float4 u = *(const float4*)(U + j * 128 + i4);
        const float4 v = *(const float4*)(V + j * 128 + i4);
        sUt[(i4 + 0) * C_WSTR + j] = u.x;
        sUt[(i4 + 1) * C_WSTR + j] = u.y;
        sUt[(i4 + 2) * C_WSTR + j] = u.z;
        sUt[(i4 + 3) * C_WSTR + j] = u.w;
        sVt[(i4 + 0) * C_WSTR + j] = v.x;
        sVt[(i4 + 1) * C_WSTR + j] = v.y;
        sVt[(i4 + 2) * C_WSTR + j] = v.z;
        sVt[(i4 + 3) * C_WSTR + j] = v.w;
    }
    // E^T fill (16 rows), vectorized reads
    for (int idx = tid; idx < C_ROWS * 32; idx += 256) {
        const int r = idx >> 5, i4 = (idx & 31) << 2;
        const float4 e = *(const float4*)(g_E + (size_t)(rowBase + r) * 128 + i4);
        sEt[(i4 + 0) * C_ASTR + r] = e.x;
        sEt[(i4 + 1) * C_ASTR + r] = e.y;
        sEt[(i4 + 2) * C_ASTR + r] = e.z;
        sEt[(i4 + 3) * C_ASTR + r] = e.w;
    }
    // neighbor indices (16*16 = 256)
    sXN[tid] = ext_nbr[(rowBase + (tid >> 4)) * 16 + (tid & 15)];
    __syncthreads();

    // Esum^T (gather 16 E rows per graph, float4)
    for (int idx = tid; idx < C_ROWS * 32; idx += 256) {
        const int r = idx >> 5, c4 = (idx & 31) << 2;
        const int* xn = &sXN[r * 16];
        float4 s = make_float4(0.f, 0.f, 0.f, 0.f);
#pragma unroll
        for (int d = 0; d < 16; ++d) {
            const float4 v = *(const float4*)(g_E + (size_t)xn[d] * 128 + c4);
            s.x += v.x; s.y += v.y; s.z += v.z; s.w += v.w;
        }
        sSt[(c4 + 0) * C_ASTR + r] = s.x;
        sSt[(c4 + 1) * C_ASTR + r] = s.y;
        sSt[(c4 + 2) * C_ASTR + r] = s.z;
        sSt[(c4 + 3) * C_ASTR + r] = s.w;
    }
    __syncthreads();

    const int tx = tid & 31;   // 4 cols
    const int ty = tid >> 5;   // warp -> 2 rows
    u64t acc[2][2] = {};       // [local row][col pair]

#pragma unroll 4
    for (int i = 0; i < 128; ++i) {
        const float2 ev = *(const float2*)(sEt + i * C_ASTR + (ty << 1));
        const float2 qv = *(const float2*)(sSt + i * C_ASTR + (ty << 1));
        const float4 uv = *(const float4*)(sUt + i * C_WSTR + (tx << 2));
        const float4 vv = *(const float4*)(sVt + i * C_WSTR + (tx << 2));
        const u64t u0 = ((const u64t*)&uv)[0], u1 = ((const u64t*)&uv)[1];
        const u64t v0 = ((const u64t*)&vv)[0], v1 = ((const u64t*)&vv)[1];
        const u64t e0 = pk2(ev.x, ev.x), e1 = pk2(ev.y, ev.y);
        const u64t s0 = pk2(qv.x, qv.x), s1 = pk2(qv.y, qv.y);
        FMA2(acc[0][0], e0, u0); FMA2(acc[0][1], e0, u1);
        FMA2(acc[1][0], e1, u0); FMA2(acc[1][1], e1, u1);
        FMA2(acc[0][0], s0, v0); FMA2(acc[0][1], s0, v1);
        FMA2(acc[1][0], s1, v0); FMA2(acc[1][1], s1, v1);
    }

#pragma unroll
    for (int rr = 0; rr < 2; ++rr) {
        const int row = rowBase + (ty << 1) + rr;
        const float2 c01 = upk2(acc[rr][0]);
        const float2 c23 = upk2(acc[rr][1]);
        float v0 = fmaxf(c01.x, 0.f), v1 = fmaxf(c01.y, 0.f);
        float v2 = fmaxf(c23.x, 0.f), v3 = fmaxf(c23.y, 0.f);
        float m = fmaxf(fmaxf(v0, v1), fmaxf(v2, v3));
#pragma unroll
        for (int off = 16; off; off >>= 1)
            m = fmaxf(m, __shfl_xor_sync(0xffffffffu, m, off));
        float e0 = expf(v0 - m), e1 = expf(v1 - m), e2 = expf(v2 - m), e3 = expf(v3 - m);
        float s = e0 + e1 + e2 + e3;
#pragma unroll
        for (int off = 16; off; off >>= 1)
            s += __shfl_xor_sync(0xffffffffu, s, off);
        const float inv = 1.f / s;
        float4 o = make_float4(e0 * inv, e1 * inv, e2 * inv, e3 * inv);
        *(float4*)(g_X + (size_t)row * 128 + (tx << 2)) = o;
    }
}

// ============================================================================
// Kernel D: ONE WAVE. 128 blocks x 8 rows; 512 threads; cp.async fill. (unchanged)
// ============================================================================
#define D2_STR 264
#define SMEM_D (128 * D2_STR * 2)

__global__ void __launch_bounds__(512) kD(const int* __restrict__ batch,
                                          const float* __restrict__ b1,
                                          const float* __restrict__ W2,
                                          const float* __restrict__ b2,
                                          float* __restrict__ out) {
    extern __shared__ __half sWh[];      // [128][D2_STR]
    __shared__ float sF[8][260];
    __shared__ float sW2[256];
    __shared__ float sB1[128];
    __shared__ float sP[16][2][2];

    const int tid = threadIdx.x;
    const int rg = tid >> 7;
    const int j = tid & 127;
    const int warp = tid >> 5, lane = tid & 31;

    const unsigned sbase = (unsigned)__cvta_generic_to_shared(sWh);
    for (int q = tid; q < 128 * 32; q += 512) {
        const int jr = q >> 5, i8 = (q & 31) << 3;
        cpa16(sbase + (jr * D2_STR + i8) * 2, g_W1h + (q << 3));
    }
    asm volatile("cp.async.commit_group;" ::: "memory");

    if (tid < 256) sW2[tid] = W2[tid];
    if (tid < 128) sB1[tid] = b1[tid];
    const float bb0 = b2[0], bb1 = b2[1];

    const int rb = rg << 1;
#pragma unroll
    for (int rr = 0; rr < 2; ++rr) {
        const int row = blockIdx.x * 8 + rb + rr;
        const int b0i = batch[2 * row];
        const int b1i = batch[2 * row + 1];
        const float e1 = g_X[b0i * 128 + j];
        const float e2 = g_X[b1i * 128 + j];
        sF[rb + rr][j] = e1 * e2;
        sF[rb + rr][128 + j] = e1 + e2;
    }
    asm volatile("cp.async.wait_group 0;" ::: "memory");
    __syncthreads();

    float4 a0 = make_float4(0.f, 0.f, 0.f, 0.f);
    float4 a1 = a0;
    const __half* wrow = sWh + j * D2_STR;
#pragma unroll 4
    for (int m = 0; m < 32; ++m) {
        const uint4 wv = *(const uint4*)(wrow + (m << 3));
        const float2 w01 = __half22float2(*(const __half2*)&wv.x);
        const float2 w23 = __half22float2(*(const __half2*)&wv.y);
        const float2 w45 = __half22float2(*(const __half2*)&wv.z);
        const float2 w67 = __half22float2(*(const __half2*)&wv.w);
        const float4 f0a = *(const float4*)(&sF[rb + 0][m << 3]);
        const float4 f0b = *(const float4*)(&sF[rb + 0][(m << 3) + 4]);
        const float4 f1a = *(const float4*)(&sF[rb + 1][m << 3]);
        const float4 f1b = *(const float4*)(&sF[rb + 1][(m << 3) + 4]);
        a0.x = fmaf(f0a.x, w01.x, a0.x); a0.y = fmaf(f0a.y, w01.y, a0.y);
        a0.z = fmaf(f0a.z, w23.x, a0.z); a0.w = fmaf(f0a.w, w23.y, a0.w);
        a0.x = fmaf(f0b.x, w45.x, a0.x); a0.y = fmaf(f0b.y, w45.y, a0.y);
        a0.z = fmaf(f0b.z, w67.x, a0.z); a0.w = fmaf(f0b.w, w67.y, a0.w);
        a1.x = fmaf(f1a.x, w01.x, a1.x); a1.y = fmaf(f1a.y, w01.y, a1.y);
        a1.z = fmaf(f1a.z, w23.x, a1.z); a1.w = fmaf(f1a.w, w23.y, a1.w);
        a1.x = fmaf(f1b.x, w45.x, a1.x); a1.y = fmaf(f1b.y, w45.y, a1.y);
        a1.z = fmaf(f1b.z, w67.x, a1.z); a1.w = fmaf(f1b.w, w67.y, a1.w);
    }

    const float bj = sB1[j];
    const float w2a = sW2[j], w2b = sW2[128 + j];
    const float h0 = fmaxf((a0.x + a0.y) + (a0.z + a0.w) + bj, 0.f);
    const float h1 = fmaxf((a1.x + a1.y) + (a1.z + a1.w) + bj, 0.f);

    float p00 = h0 * w2a, p01 = h0 * w2b;
    float p10 = h1 * w2a, p11 = h1 * w2b;
#pragma unroll
    for (int off = 16; off; off >>= 1) {
        p00 += __shfl_xor_sync(0xffffffffu, p00, off);
        p01 += __shfl_xor_sync(0xffffffffu, p01, off);
        p10 += __shfl_xor_sync(0xffffffffu, p10, off);
        p11 += __shfl_xor_sync(0xffffffffu, p11, off);
    }
    if (lane == 0) {
        sP[warp][0][0] = p00; sP[warp][0][1] = p01;
        sP[warp][1][0] = p10; sP[warp][1][1] = p11;
    }
    __syncthreads();

    if (tid < 8) {
        const int r = tid;
        const int wbase = (r >> 1) << 2;
        const int lr = r & 1;
        const int row = blockIdx.x * 8 + r;
        float o0 = bb0, o1 = bb1;
#pragma unroll
        for (int w2 = 0; w2 < 4; ++w2) {
            o0 += sP[wbase + w2][lr][0];
            o1 += sP[wbase + w2][lr][1];
        }
        const float mm = fmaxf(o0, o1);
        const float z0 = expf(o0 - mm), z1 = expf(o1 - mm);
        const float inv = 1.f / (z0 + z1);
        out[row * 2]     = z0 * inv;
        out[row * 2 + 1] = z1 * inv;
    }
}

// ============================================================================
extern "C" void kernel_launch(void* const* d_in, const int* in_sizes, int n_in,
                              void* d_out, int out_size) {
    const int*   batch     = (const int*)d_in[0];
    const int*   node_type = (const int*)d_in[1];
    const int*   nbr_type  = (const int*)d_in[2];
    const int*   ext_nbr   = (const int*)d_in[3];
    const float* impact    = (const float*)d_in[4];
    const float* W         = (const float*)d_in[5];
    const float* M         = (const float*)d_in[6];
    const float* U         = (const float*)d_in[7];
    const float* V         = (const float*)d_in[8];
    const float* W1        = (const float*)d_in[9];
    const float* b1        = (const float*)d_in[10];
    const float* W2        = (const float*)d_in[11];
    const float* b2        = (const float*)d_in[12];
    float* out = (float*)d_out;

    cudaFuncSetAttribute(kA, cudaFuncAttributeMaxDynamicSharedMemorySize, SMEM_A);
    cudaFuncSetAttribute(kC, cudaFuncAttributeMaxDynamicSharedMemorySize, SMEM_C);
    cudaFuncSetAttribute(kD, cudaFuncAttributeMaxDynamicSharedMemorySize, SMEM_D);

    // diagnostic: one dummy -> ncu's -s window lands on kC (verify the fix)
    kNop<<<1, 32>>>();

    kA<<<(NTYPES + 127) / 128, 256, SMEM_A>>>(impact, W, M, W1);
    kB<<<NG, 256>>>(node_type, nbr_type);
    kC<<<NG / C_ROWS, 256, SMEM_C>>>(U, V, ext_nbr);
    kD<<<NB / 8, 512, SMEM_D>>>(batch, b1, W2, b2, out);
}